// round 10
// baseline (speedup 1.0000x reference)
#include <cuda_runtime.h>
#include <math.h>
#include <stdint.h>

#define B_SZ 512
#define D_SZ 512
#define C_SZ 100000
#define BN 128
#define BM 128
#define BKB 64                     // K bytes per stage step (64 int8)
#define NK 8                       // 512/64
#define NSTAGE 3
#define NTILES_N 782               // ceil(100000/128)
#define C_PAD (NTILES_N * BN)      // 100096 (pad rows stay zero, scale 0)
#define PITCH 80                   // bytes per smem row (64 data + 16 pad)
#define B_PART (128 * PITCH)       // 10240
#define STAGE_SZ (2 * B_PART)      // 20480
#define SW_OFF (NSTAGE * STAGE_SZ) // 61440
#define SMEM_BYTES (SW_OFF + BN * 4)  // 61952
#define S_SCALE 30.0f
#define LMAX 31.0f
#define COS_M 0.8775825618903728f
#define SIN_M 0.47942553860420300f

// ---------------- static device scratch -------------------------------------
__device__ uint32_t g_wq[(size_t)C_PAD * 128];   // int8-packed normalized w
__device__ uint32_t g_xq[B_SZ * 128];            // int8-packed normalized x
__device__ float g_sw[C_PAD];                    // per-class scale (incl. 1/||w||)
__device__ float g_sx[B_SZ];                     // per-row x scale
__device__ float g_xn[B_SZ * D_SZ];              // normalized fp32 x (finalize)
__device__ float g_rowsum[B_SZ];

// ---------------- PTX helpers ------------------------------------------------
__device__ __forceinline__ uint32_t smem_u32(const void* p) {
    uint32_t a;
    asm("{ .reg .u64 t; cvta.to.shared.u64 t, %1; cvt.u32.u64 %0, t; }" : "=r"(a) : "l"(p));
    return a;
}
__device__ __forceinline__ void cp16(uint32_t dst, const void* src) {
    asm volatile("cp.async.cg.shared.global [%0], [%1], 16;" :: "r"(dst), "l"(src));
}
#define CP_COMMIT() asm volatile("cp.async.commit_group;" ::: "memory")
#define CP_WAIT(n)  asm volatile("cp.async.wait_group %0;" :: "n"(n) : "memory")

__device__ __forceinline__ void ldsm4(uint32_t* r, uint32_t addr) {
    asm volatile("ldmatrix.sync.aligned.m8n8.x4.shared.b16 {%0,%1,%2,%3}, [%4];"
        : "=r"(r[0]), "=r"(r[1]), "=r"(r[2]), "=r"(r[3]) : "r"(addr));
}
__device__ __forceinline__ void mma16832s8(int* d, const uint32_t* a, uint32_t b0, uint32_t b1) {
    asm volatile(
        "mma.sync.aligned.m16n8k32.row.col.s32.s8.s8.s32 "
        "{%0,%1,%2,%3}, {%4,%5,%6,%7}, {%8,%9}, {%0,%1,%2,%3};"
        : "+r"(d[0]), "+r"(d[1]), "+r"(d[2]), "+r"(d[3])
        : "r"(a[0]), "r"(a[1]), "r"(a[2]), "r"(a[3]), "r"(b0), "r"(b1));
}
__device__ __forceinline__ uint32_t pack_s8(float a, float b, float c, float d) {
    int i0 = __float2int_rn(a), i1 = __float2int_rn(b);
    int i2 = __float2int_rn(c), i3 = __float2int_rn(d);
    i0 = max(-127, min(127, i0)); i1 = max(-127, min(127, i1));
    i2 = max(-127, min(127, i2)); i3 = max(-127, min(127, i3));
    return (uint32_t)(i0 & 0xff) | ((uint32_t)(i1 & 0xff) << 8) |
           ((uint32_t)(i2 & 0xff) << 16) | ((uint32_t)(i3 & 0xff) << 24);
}

// ---------------------------------------------------------------------------
// Kernel 1: normalize x rows -> g_xn fp32 + int8 quantized g_xq/g_sx.
// ---------------------------------------------------------------------------
__global__ void xnorm_kernel(const float* __restrict__ x, float* __restrict__ out) {
    const int row = blockIdx.x;
    const int tid = threadIdx.x;   // 128
    float4 v = reinterpret_cast<const float4*>(x + (size_t)row * D_SZ)[tid];

    __shared__ float red[128];
    red[tid] = v.x * v.x + v.y * v.y + v.z * v.z + v.w * v.w;
    __syncthreads();
    #pragma unroll
    for (int off = 64; off > 0; off >>= 1) {
        if (tid < off) red[tid] += red[tid + off];
        __syncthreads();
    }
    const float inv = 1.f / fmaxf(sqrtf(red[0]), 1e-12f);
    __syncthreads();

    float4 nv = make_float4(v.x * inv, v.y * inv, v.z * inv, v.w * inv);
    reinterpret_cast<float4*>(g_xn + (size_t)row * D_SZ)[tid] = nv;

    // row max(|nv|)
    red[tid] = fmaxf(fmaxf(fabsf(nv.x), fabsf(nv.y)), fmaxf(fabsf(nv.z), fabsf(nv.w)));
    __syncthreads();
    #pragma unroll
    for (int off = 64; off > 0; off >>= 1) {
        if (tid < off) red[tid] = fmaxf(red[tid], red[tid + off]);
        __syncthreads();
    }
    const float mx = red[0];
    const float qs = (mx > 0.f) ? 127.f / mx : 0.f;
    g_xq[row * 128 + tid] = pack_s8(nv.x * qs, nv.y * qs, nv.z * qs, nv.w * qs);
    if (tid == 0) {
        g_sx[row] = mx * (1.f / 127.f);
        g_rowsum[row] = 0.f;
        if (row == 0) out[0] = 0.f;
    }
}

// ---------------------------------------------------------------------------
// Kernel 2: normalize + int8-quantize weight rows (one warp per row; pads=0)
// ---------------------------------------------------------------------------
__global__ void wquant_kernel(const float* __restrict__ w) {
    const int warp = threadIdx.x >> 5;
    const int lane = threadIdx.x & 31;
    const int c = blockIdx.x * 8 + warp;        // grid 12512 -> C_PAD rows

    float4 v[4];
    float ss = 0.f;
    if (c < C_SZ) {
        const float4* wr = reinterpret_cast<const float4*>(w + (size_t)c * D_SZ);
        #pragma unroll
        for (int i = 0; i < 4; i++) {
            v[i] = wr[lane + i * 32];
            ss += v[i].x * v[i].x + v[i].y * v[i].y + v[i].z * v[i].z + v[i].w * v[i].w;
        }
    } else {
        #pragma unroll
        for (int i = 0; i < 4; i++) v[i] = make_float4(0.f, 0.f, 0.f, 0.f);
    }
    #pragma unroll
    for (int m = 16; m > 0; m >>= 1)
        ss += __shfl_xor_sync(0xffffffffu, ss, m);
    const float inv = 1.f / fmaxf(sqrtf(ss), 1e-12f);

    float mx = 0.f;
    #pragma unroll
    for (int i = 0; i < 4; i++) {
        v[i].x *= inv; v[i].y *= inv; v[i].z *= inv; v[i].w *= inv;
        mx = fmaxf(mx, fmaxf(fmaxf(fabsf(v[i].x), fabsf(v[i].y)),
                             fmaxf(fabsf(v[i].z), fabsf(v[i].w))));
    }
    #pragma unroll
    for (int m = 16; m > 0; m >>= 1)
        mx = fmaxf(mx, __shfl_xor_sync(0xffffffffu, mx, m));
    const float qs = (mx > 0.f) ? 127.f / mx : 0.f;

    uint32_t* dst = g_wq + (size_t)c * 128;
    #pragma unroll
    for (int i = 0; i < 4; i++)
        dst[lane + i * 32] = pack_s8(v[i].x * qs, v[i].y * qs, v[i].z * qs, v[i].w * qs);
    if (lane == 0) g_sw[c] = mx * (1.f / 127.f);
}

// ---------------------------------------------------------------------------
// Kernel 3: fused int8 IMMA GEMM + streaming exp-sum epilogue.
// CTA 128x128xK512 (int8). 3-stage cp.async ring, BKB=64 bytes/step,
// R8-proven barrier structure. Grid (m=4, n=782).
// ---------------------------------------------------------------------------
__global__ void __launch_bounds__(256, 2) gemm_fused_kernel() {
    extern __shared__ __align__(16) char smem[];
    const int tid = threadIdx.x;
    const int warp = tid >> 5;
    const int lane = tid & 31;
    const int wm = warp & 1;
    const int wn = warp >> 1;
    const int m0 = blockIdx.x * BM;
    const int n0 = blockIdx.y * BN;
    const uint32_t sb = smem_u32(smem);
    float* sws = reinterpret_cast<float*>(smem + SW_OFF);

    const char* srcA = (const char*)g_xq + (size_t)m0 * 512;
    const char* srcB = (const char*)g_wq + (size_t)n0 * 512;

    // per-class scales into smem (visible after the k=0 barrier)
    if (tid < BN) sws[tid] = g_sw[n0 + tid] * S_SCALE;

    int acc[4][4][4];
    #pragma unroll
    for (int a = 0; a < 4; a++)
        #pragma unroll
        for (int b = 0; b < 4; b++)
            #pragma unroll
            for (int c = 0; c < 4; c++) acc[a][b][c] = 0;

    // stage loader: 1024 cp16 (A: 128x64B, B: 128x64B), 4 per thread
    auto load_stage = [&](int stage, int k0) {
        const uint32_t dst = sb + (uint32_t)stage * STAGE_SZ;
        #pragma unroll
        for (int j = 0; j < 4; j++) {
            int idx = tid + 256 * j;            // 0..1023
            int row = (idx >> 2) & 127;
            int piece = idx & 3;
            uint32_t doff = (uint32_t)(row * PITCH + piece * 16);
            if (idx < 512)
                cp16(dst + doff, srcA + (size_t)row * 512 + k0 + piece * 16);
            else
                cp16(dst + B_PART + doff, srcB + (size_t)row * 512 + k0 + piece * 16);
        }
    };

    load_stage(0, 0);
    CP_COMMIT();
    load_stage(1, BKB);
    CP_COMMIT();

    const int lrow = lane & 15;
    const int lcolb = (lane >> 4) * 16;

    for (int k = 0; k < NK; k++) {
        if (k == NK - 1) { CP_WAIT(0); } else { CP_WAIT(1); }
        __syncthreads();

        const uint32_t aoff = sb + (uint32_t)(k % NSTAGE) * STAGE_SZ;
        const uint32_t boff = aoff + B_PART;
        #pragma unroll
        for (int kk = 0; kk < BKB; kk += 32) {
            uint32_t af[4][4], bf[2][4];
            #pragma unroll
            for (int mt = 0; mt < 4; mt++)
                ldsm4(af[mt], aoff + (uint32_t)((wm * 64 + mt * 16 + lrow) * PITCH) + kk + lcolb);
            #pragma unroll
            for (int nt2 = 0; nt2 < 2; nt2++)
                ldsm4(bf[nt2], boff + (uint32_t)((wn * 32 + nt2 * 16 + lrow) * PITCH) + kk + lcolb);
            #pragma unroll
            for (int mt = 0; mt < 4; mt++) {
                #pragma unroll
                for (int nt = 0; nt < 4; nt++) {
                    const uint32_t* bb = bf[nt >> 1];
                    uint32_t b0 = (nt & 1) ? bb[1] : bb[0];
                    uint32_t b1 = (nt & 1) ? bb[3] : bb[2];
                    mma16832s8(acc[mt][nt], af[mt], b0, b1);
                }
            }
        }
        __syncthreads();   // all warps done reading stage k before it is refilled

        if (k + 2 < NK) {
            load_stage((k + 2) % NSTAGE, (k + 2) * BKB);
            CP_COMMIT();
        }
    }

    // ---- epilogue: logit = acc*sx*sw*30; exp-sum per row -> atomic ---------
    // pad classes have sw=0 -> logit 0 -> exp(-31) ~ 3e-14 (negligible).
    const int rbase = m0 + wm * 64 + (lane >> 2);
    const int cl = wn * 32 + 2 * (lane & 3);

    #pragma unroll
    for (int mt = 0; mt < 4; mt++) {
        const float s0 = g_sx[rbase + mt * 16];
        const float s1 = g_sx[rbase + mt * 16 + 8];
        float es0 = 0.f, es1 = 0.f;
        #pragma unroll
        for (int nt = 0; nt < 4; nt++) {
            const int c0 = cl + nt * 8;
            const float sw0 = sws[c0], sw1 = sws[c0 + 1];
            es0 += __expf(fmaf((float)acc[mt][nt][0], s0 * sw0, -LMAX));
            es0 += __expf(fmaf((float)acc[mt][nt][1], s0 * sw1, -LMAX));
            es1 += __expf(fmaf((float)acc[mt][nt][2], s1 * sw0, -LMAX));
            es1 += __expf(fmaf((float)acc[mt][nt][3], s1 * sw1, -LMAX));
        }
        es0 += __shfl_xor_sync(0xffffffffu, es0, 1);
        es0 += __shfl_xor_sync(0xffffffffu, es0, 2);
        es1 += __shfl_xor_sync(0xffffffffu, es1, 1);
        es1 += __shfl_xor_sync(0xffffffffu, es1, 2);
        if ((lane & 3) == 0) {
            atomicAdd(&g_rowsum[rbase + mt * 16], es0);
            atomicAdd(&g_rowsum[rbase + mt * 16 + 8], es1);
        }
    }
}

// ---------------------------------------------------------------------------
// Kernel 4: finalize — exact fp32 target dot + norm, margin swap, nll,
// atomic mean into out[0].
// ---------------------------------------------------------------------------
__global__ void finalize_kernel(const float* __restrict__ w,
                                const int* __restrict__ tgt,
                                float* __restrict__ out) {
    const int b = blockIdx.x;
    const int tid = threadIdx.x;   // 256
    __shared__ float sd[256], sn[256];

    const int t = tgt[b];
    const float* wr = w + (size_t)t * D_SZ;
    const float* xr = g_xn + (size_t)b * D_SZ;
    float w0 = wr[tid], w1 = wr[tid + 256];
    sd[tid] = xr[tid] * w0 + xr[tid + 256] * w1;
    sn[tid] = w0 * w0 + w1 * w1;
    __syncthreads();
    #pragma unroll
    for (int off = 128; off > 0; off >>= 1) {
        if (tid < off) { sd[tid] += sd[tid + off]; sn[tid] += sn[tid + off]; }
        __syncthreads();
    }

    if (tid == 0) {
        float winv = 1.f / fmaxf(sqrtf(sn[0]), 1e-12f);
        float cosv = sd[0] * winv;
        float sinv = sqrtf(fmaxf(1.f - cosv * cosv, 0.f));
        float phi = cosv * COS_M - sinv * SIN_M;
        float adj = (cosv > 0.f) ? phi : cosv;          // easy margin
        float lt = S_SCALE * adj;
        float lo = S_SCALE * cosv;
        float s2 = g_rowsum[b] - expf(lo - LMAX) + expf(lt - LMAX);
        float nll = LMAX + logf(s2) - lt;
        atomicAdd(out, nll * (1.f / (float)B_SZ));
    }
}

// ---------------------------------------------------------------------------
extern "C" void kernel_launch(void* const* d_in, const int* in_sizes, int n_in,
                              void* d_out, int out_size) {
    const float* x = (const float*)d_in[0];
    const float* w = (const float*)d_in[1];
    const int* tgt = (const int*)d_in[2];
    float* out = (float*)d_out;

    cudaFuncSetAttribute(gemm_fused_kernel,
                         cudaFuncAttributeMaxDynamicSharedMemorySize, SMEM_BYTES);

    xnorm_kernel<<<B_SZ, 128>>>(x, out);
    wquant_kernel<<<C_PAD / 8, 256>>>(w);
    dim3 grid(B_SZ / BM, NTILES_N);
    gemm_fused_kernel<<<grid, 256, SMEM_BYTES>>>();
    finalize_kernel<<<B_SZ, 256>>>(w, tgt, out);
}

// round 11
// speedup vs baseline: 1.9107x; 1.9107x over previous
#include <cuda_runtime.h>
#include <cuda_bf16.h>
#include <math.h>
#include <stdint.h>

#define B_SZ 512
#define D_SZ 512
#define C_SZ 100000
#define BN 128
#define BM 128
#define BK 64
#define NK 8                       // 512/64
#define NSTAGE 3
#define NTILES_N 782               // ceil(100000/128)
#define C_PAD (NTILES_N * BN)      // 100096 (pad rows stay zero)
#define PITCH 72                   // halves per smem row (144 B) — conflict-free ldsm
#define STAGE_B (2 * 128 * PITCH * 2)      // A half + B half = 36864 B
#define B_PART  (128 * PITCH * 2)          // 18432
#define SMEM_BYTES (NSTAGE * STAGE_B)      // 110592
#define S_SCALE 30.0f
#define LMAX 31.0f
#define COS_M 0.8775825618903728f
#define SIN_M 0.47942553860420300f

// ---------------- static device scratch -------------------------------------
__device__ __nv_bfloat16 g_wn[(size_t)C_PAD * D_SZ];   // normalized bf16 w
__device__ __nv_bfloat16 g_xnbf[B_SZ * D_SZ];
__device__ float g_xn[B_SZ * D_SZ];
__device__ float g_rowsum[B_SZ];

// ---------------- PTX helpers ------------------------------------------------
__device__ __forceinline__ uint32_t smem_u32(const void* p) {
    uint32_t a;
    asm("{ .reg .u64 t; cvta.to.shared.u64 t, %1; cvt.u32.u64 %0, t; }" : "=r"(a) : "l"(p));
    return a;
}
__device__ __forceinline__ void cp16(uint32_t dst, const void* src) {
    asm volatile("cp.async.cg.shared.global [%0], [%1], 16;" :: "r"(dst), "l"(src));
}
#define CP_COMMIT() asm volatile("cp.async.commit_group;" ::: "memory")
#define CP_WAIT(n)  asm volatile("cp.async.wait_group %0;" :: "n"(n) : "memory")

__device__ __forceinline__ void ldsm4(uint32_t* r, uint32_t addr) {
    asm volatile("ldmatrix.sync.aligned.m8n8.x4.shared.b16 {%0,%1,%2,%3}, [%4];"
        : "=r"(r[0]), "=r"(r[1]), "=r"(r[2]), "=r"(r[3]) : "r"(addr));
}
__device__ __forceinline__ void mma16816(float* d, const uint32_t* a, uint32_t b0, uint32_t b1) {
    asm volatile(
        "mma.sync.aligned.m16n8k16.row.col.f32.bf16.bf16.f32 "
        "{%0,%1,%2,%3}, {%4,%5,%6,%7}, {%8,%9}, {%0,%1,%2,%3};"
        : "+f"(d[0]), "+f"(d[1]), "+f"(d[2]), "+f"(d[3])
        : "r"(a[0]), "r"(a[1]), "r"(a[2]), "r"(a[3]), "r"(b0), "r"(b1));
}

// ---------------------------------------------------------------------------
// Kernel 1: normalize x rows -> g_xn (fp32) + g_xnbf (bf16); zero g_rowsum
// and the output scalar (block 0).
// ---------------------------------------------------------------------------
__global__ void xnorm_kernel(const float* __restrict__ x, float* __restrict__ out) {
    const int row = blockIdx.x;
    const int tid = threadIdx.x;   // 128
    const float* xr = x + (size_t)row * D_SZ;

    float ss = 0.f;
    float v[4];
    #pragma unroll
    for (int i = 0; i < 4; i++) { v[i] = xr[tid + i * 128]; ss += v[i] * v[i]; }
    __shared__ float red[128];
    red[tid] = ss;
    __syncthreads();
    #pragma unroll
    for (int off = 64; off > 0; off >>= 1) {
        if (tid < off) red[tid] += red[tid + off];
        __syncthreads();
    }
    const float inv = 1.f / fmaxf(sqrtf(red[0]), 1e-12f);
    #pragma unroll
    for (int i = 0; i < 4; i++) {
        int d = tid + i * 128;
        float nv = v[i] * inv;
        g_xn[(size_t)row * D_SZ + d] = nv;
        g_xnbf[(size_t)row * D_SZ + d] = __float2bfloat16_rn(nv);
    }
    if (tid == 0) {
        g_rowsum[row] = 0.f;
        if (row == 0) out[0] = 0.f;
    }
}

// ---------------------------------------------------------------------------
// Kernel 2: normalize weight rows + convert to bf16 (one warp per row)
// ---------------------------------------------------------------------------
__global__ void wconv_kernel(const float* __restrict__ w) {
    const int warp = threadIdx.x >> 5;
    const int lane = threadIdx.x & 31;
    const int c = blockIdx.x * 8 + warp;       // grid 12500 -> 100000 rows
    const float4* wr = reinterpret_cast<const float4*>(w + (size_t)c * D_SZ);

    float4 v[4];
    float ss = 0.f;
    #pragma unroll
    for (int i = 0; i < 4; i++) {
        v[i] = wr[lane + i * 32];
        ss += v[i].x * v[i].x + v[i].y * v[i].y + v[i].z * v[i].z + v[i].w * v[i].w;
    }
    #pragma unroll
    for (int m = 16; m > 0; m >>= 1)
        ss += __shfl_xor_sync(0xffffffffu, ss, m);
    const float inv = 1.f / fmaxf(sqrtf(ss), 1e-12f);

    uint2* dst = reinterpret_cast<uint2*>(g_wn + (size_t)c * D_SZ);
    #pragma unroll
    for (int i = 0; i < 4; i++) {
        __nv_bfloat162 p0 = __floats2bfloat162_rn(v[i].x * inv, v[i].y * inv);
        __nv_bfloat162 p1 = __floats2bfloat162_rn(v[i].z * inv, v[i].w * inv);
        uint2 o;
        o.x = *reinterpret_cast<uint32_t*>(&p0);
        o.y = *reinterpret_cast<uint32_t*>(&p1);
        dst[lane + i * 32] = o;
    }
}

// ---------------------------------------------------------------------------
// Kernel 3: fused HMMA GEMM + streaming exp-sum epilogue.
// CTA 128x128xK512. 3-stage cp.async ring, BK=64, R8 barrier structure,
// grid (m=4, n=782). NEW: fragment double-buffering — ldmatrix for chunk
// kk+1 issues before the MMAs of chunk kk, hiding LDSM latency under the
// tensor pipe.
// ---------------------------------------------------------------------------
__global__ void __launch_bounds__(256, 1) gemm_fused_kernel() {
    extern __shared__ __align__(16) char smem[];
    const int tid = threadIdx.x;
    const int warp = tid >> 5;
    const int lane = tid & 31;
    const int wm = warp & 1;
    const int wn = warp >> 1;
    const int m0 = blockIdx.x * BM;
    const int n0 = blockIdx.y * BN;
    const uint32_t sb = smem_u32(smem);

    const __nv_bfloat16* srcA = g_xnbf + (size_t)m0 * D_SZ;
    const __nv_bfloat16* srcB = g_wn + (size_t)n0 * D_SZ;

    float acc[4][4][4];
    #pragma unroll
    for (int a = 0; a < 4; a++)
        #pragma unroll
        for (int b = 0; b < 4; b++)
            #pragma unroll
            for (int c = 0; c < 4; c++) acc[a][b][c] = 0.f;

    // stage loader: 2048 cp16 (A: 128x64 halves, B: 128x64 halves), 8/thread
    auto load_stage = [&](int stage, int k0) {
        const uint32_t dst = sb + (uint32_t)stage * STAGE_B;
        #pragma unroll
        for (int j = 0; j < 8; j++) {
            int idx = tid + 256 * j;            // 0..2047
            int row = (idx >> 3) & 127;
            int piece = idx & 7;
            uint32_t doff = (uint32_t)(row * (PITCH * 2) + piece * 16);
            if (idx < 1024)
                cp16(dst + doff, srcA + (size_t)row * D_SZ + k0 + piece * 8);
            else
                cp16(dst + B_PART + doff, srcB + (size_t)row * D_SZ + k0 + piece * 8);
        }
    };

    load_stage(0, 0);
    CP_COMMIT();
    load_stage(1, BK);
    CP_COMMIT();

    const int lrow = lane & 15;
    const int lcol = (lane >> 4) * 8;

    // double-buffered fragments
    uint32_t af[2][4][4], bf[2][2][4];
    auto ldfrags = [&](uint32_t aoff, uint32_t boff, int kk, int buf) {
        #pragma unroll
        for (int mt = 0; mt < 4; mt++)
            ldsm4(af[buf][mt], aoff + (uint32_t)((wm * 64 + mt * 16 + lrow) * PITCH + kk + lcol) * 2);
        #pragma unroll
        for (int nt2 = 0; nt2 < 2; nt2++)
            ldsm4(bf[buf][nt2], boff + (uint32_t)((wn * 32 + nt2 * 16 + lrow) * PITCH + kk + lcol) * 2);
    };

    for (int k = 0; k < NK; k++) {
        if (k == NK - 1) { CP_WAIT(0); } else { CP_WAIT(1); }
        __syncthreads();

        const uint32_t aoff = sb + (uint32_t)(k % NSTAGE) * STAGE_B;
        const uint32_t boff = aoff + B_PART;

        ldfrags(aoff, boff, 0, 0);
        #pragma unroll
        for (int c4 = 0; c4 < 4; c4++) {           // kk = c4*16
            const int cur = c4 & 1;
            if (c4 < 3) ldfrags(aoff, boff, (c4 + 1) * 16, cur ^ 1);
            #pragma unroll
            for (int mt = 0; mt < 4; mt++) {
                #pragma unroll
                for (int nt = 0; nt < 4; nt++) {
                    const uint32_t* bb = bf[cur][nt >> 1];
                    uint32_t b0 = (nt & 1) ? bb[1] : bb[0];
                    uint32_t b1 = (nt & 1) ? bb[3] : bb[2];
                    mma16816(acc[mt][nt], af[cur][mt], b0, b1);
                }
            }
        }
        __syncthreads();   // all warps done reading stage k before it is refilled

        if (k + 2 < NK) {
            load_stage((k + 2) % NSTAGE, (k + 2) * BK);
            CP_COMMIT();
        }
    }

    // ---- epilogue: exp-sum per batch row, atomic into g_rowsum -------------
    const bool edge = (n0 + BN > C_SZ);
    const int rbase = m0 + wm * 64 + (lane >> 2);
    const int cbase = n0 + wn * 32 + 2 * (lane & 3);

    #pragma unroll
    for (int mt = 0; mt < 4; mt++) {
        float es0 = 0.f, es1 = 0.f;
        #pragma unroll
        for (int nt = 0; nt < 4; nt++) {
            const int c0 = cbase + nt * 8;
            if (!edge) {
                es0 += __expf(fmaf(acc[mt][nt][0], S_SCALE, -LMAX));
                es0 += __expf(fmaf(acc[mt][nt][1], S_SCALE, -LMAX));
                es1 += __expf(fmaf(acc[mt][nt][2], S_SCALE, -LMAX));
                es1 += __expf(fmaf(acc[mt][nt][3], S_SCALE, -LMAX));
            } else {
                if (c0 < C_SZ)     { es0 += __expf(fmaf(acc[mt][nt][0], S_SCALE, -LMAX));
                                     es1 += __expf(fmaf(acc[mt][nt][2], S_SCALE, -LMAX)); }
                if (c0 + 1 < C_SZ) { es0 += __expf(fmaf(acc[mt][nt][1], S_SCALE, -LMAX));
                                     es1 += __expf(fmaf(acc[mt][nt][3], S_SCALE, -LMAX)); }
            }
        }
        es0 += __shfl_xor_sync(0xffffffffu, es0, 1);
        es0 += __shfl_xor_sync(0xffffffffu, es0, 2);
        es1 += __shfl_xor_sync(0xffffffffu, es1, 1);
        es1 += __shfl_xor_sync(0xffffffffu, es1, 2);
        if ((lane & 3) == 0) {
            atomicAdd(&g_rowsum[rbase + mt * 16], es0);
            atomicAdd(&g_rowsum[rbase + mt * 16 + 8], es1);
        }
    }
}

// ---------------------------------------------------------------------------
// Kernel 4: finalize — exact fp32 target dot + target norm, margin swap, nll;
// atomic mean accumulation into out[0] (zeroed by xnorm).
// ---------------------------------------------------------------------------
__global__ void finalize_kernel(const float* __restrict__ w,
                                const int* __restrict__ tgt,
                                float* __restrict__ out) {
    const int b = blockIdx.x;
    const int tid = threadIdx.x;   // 256
    __shared__ float sd[256], sn[256];

    const int t = tgt[b];
    const float* wr = w + (size_t)t * D_SZ;
    const float* xr = g_xn + (size_t)b * D_SZ;
    float w0 = wr[tid], w1 = wr[tid + 256];
    sd[tid] = xr[tid] * w0 + xr[tid + 256] * w1;
    sn[tid] = w0 * w0 + w1 * w1;
    __syncthreads();
    #pragma unroll
    for (int off = 128; off > 0; off >>= 1) {
        if (tid < off) { sd[tid] += sd[tid + off]; sn[tid] += sn[tid + off]; }
        __syncthreads();
    }

    if (tid == 0) {
        float winv = 1.f / fmaxf(sqrtf(sn[0]), 1e-12f);
        float cosv = sd[0] * winv;
        float sinv = sqrtf(fmaxf(1.f - cosv * cosv, 0.f));
        float phi = cosv * COS_M - sinv * SIN_M;
        float adj = (cosv > 0.f) ? phi : cosv;          // easy margin
        float lt = S_SCALE * adj;
        float lo = S_SCALE * cosv;
        float s2 = g_rowsum[b] - expf(lo - LMAX) + expf(lt - LMAX);
        float nll = LMAX + logf(s2) - lt;
        atomicAdd(out, nll * (1.f / (float)B_SZ));
    }
}

// ---------------------------------------------------------------------------
extern "C" void kernel_launch(void* const* d_in, const int* in_sizes, int n_in,
                              void* d_out, int out_size) {
    const float* x = (const float*)d_in[0];
    const float* w = (const float*)d_in[1];
    const int* tgt = (const int*)d_in[2];
    float* out = (float*)d_out;

    cudaFuncSetAttribute(gemm_fused_kernel,
                         cudaFuncAttributeMaxDynamicSharedMemorySize, SMEM_BYTES);

    xnorm_kernel<<<B_SZ, 128>>>(x, out);
    wconv_kernel<<<C_SZ / 8, 256>>>(w);
    dim3 grid(B_SZ / BM, NTILES_N);
    gemm_fused_kernel<<<grid, 256, SMEM_BYTES>>>();
    finalize_kernel<<<B_SZ, 256>>>(w, tgt, out);
}

// round 12
// speedup vs baseline: 1.9716x; 1.0319x over previous
#include <cuda_runtime.h>
#include <cuda_fp16.h>
#include <math.h>
#include <stdint.h>

#define B_SZ 512
#define D_SZ 512
#define C_SZ 100000
#define BN 128
#define BM 128
#define BK 64
#define NK 8                       // 512/64
#define NSTAGE 3
#define NTILES_N 782               // ceil(100000/128)
#define C_PAD (NTILES_N * BN)      // 100096 (pad rows stay zero)
#define PITCH 72                   // halves per smem row (144 B) — conflict-free ldsm
#define STAGE_B (2 * 128 * PITCH * 2)      // A half + B half = 36864 B
#define B_PART  (128 * PITCH * 2)          // 18432
#define SMEM_BYTES (NSTAGE * STAGE_B)      // 110592
#define S_SCALE 30.0f
#define LMAX 31.0f
#define COS_M 0.8775825618903728f
#define SIN_M 0.47942553860420300f

// ---------------- static device scratch -------------------------------------
__device__ __half g_wh[(size_t)C_PAD * D_SZ];   // normalized fp16 w
__device__ __half g_xh[B_SZ * D_SZ];            // normalized fp16 x
__device__ float g_xn[B_SZ * D_SZ];
__device__ float g_rowsum[B_SZ];

// ---------------- PTX helpers ------------------------------------------------
__device__ __forceinline__ uint32_t smem_u32(const void* p) {
    uint32_t a;
    asm("{ .reg .u64 t; cvta.to.shared.u64 t, %1; cvt.u32.u64 %0, t; }" : "=r"(a) : "l"(p));
    return a;
}
__device__ __forceinline__ void cp16(uint32_t dst, const void* src) {
    asm volatile("cp.async.cg.shared.global [%0], [%1], 16;" :: "r"(dst), "l"(src));
}
#define CP_COMMIT() asm volatile("cp.async.commit_group;" ::: "memory")
#define CP_WAIT(n)  asm volatile("cp.async.wait_group %0;" :: "n"(n) : "memory")

__device__ __forceinline__ void ldsm4(uint32_t* r, uint32_t addr) {
    asm volatile("ldmatrix.sync.aligned.m8n8.x4.shared.b16 {%0,%1,%2,%3}, [%4];"
        : "=r"(r[0]), "=r"(r[1]), "=r"(r[2]), "=r"(r[3]) : "r"(addr));
}
// fp16 inputs, fp16 accumulators (D/C = f16): candidate 2x-rate path
__device__ __forceinline__ void mma16816h(uint32_t* d, const uint32_t* a, uint32_t b0, uint32_t b1) {
    asm volatile(
        "mma.sync.aligned.m16n8k16.row.col.f16.f16.f16.f16 "
        "{%0,%1}, {%2,%3,%4,%5}, {%6,%7}, {%0,%1};"
        : "+r"(d[0]), "+r"(d[1])
        : "r"(a[0]), "r"(a[1]), "r"(a[2]), "r"(a[3]), "r"(b0), "r"(b1));
}

// ---------------------------------------------------------------------------
// Kernel 1: normalize x rows -> g_xn (fp32) + g_xh (fp16); zero g_rowsum/out
// ---------------------------------------------------------------------------
__global__ void xnorm_kernel(const float* __restrict__ x, float* __restrict__ out) {
    const int row = blockIdx.x;
    const int tid = threadIdx.x;   // 128
    const float* xr = x + (size_t)row * D_SZ;

    float ss = 0.f;
    float v[4];
    #pragma unroll
    for (int i = 0; i < 4; i++) { v[i] = xr[tid + i * 128]; ss += v[i] * v[i]; }
    __shared__ float red[128];
    red[tid] = ss;
    __syncthreads();
    #pragma unroll
    for (int off = 64; off > 0; off >>= 1) {
        if (tid < off) red[tid] += red[tid + off];
        __syncthreads();
    }
    const float inv = 1.f / fmaxf(sqrtf(red[0]), 1e-12f);
    #pragma unroll
    for (int i = 0; i < 4; i++) {
        int d = tid + i * 128;
        float nv = v[i] * inv;
        g_xn[(size_t)row * D_SZ + d] = nv;
        g_xh[(size_t)row * D_SZ + d] = __float2half_rn(nv);
    }
    if (tid == 0) {
        g_rowsum[row] = 0.f;
        if (row == 0) out[0] = 0.f;
    }
}

// ---------------------------------------------------------------------------
// Kernel 2: normalize weight rows + convert to fp16 (one warp per row)
// ---------------------------------------------------------------------------
__global__ void wconv_kernel(const float* __restrict__ w) {
    const int warp = threadIdx.x >> 5;
    const int lane = threadIdx.x & 31;
    const int c = blockIdx.x * 8 + warp;       // grid 12500 -> 100000 rows
    const float4* wr = reinterpret_cast<const float4*>(w + (size_t)c * D_SZ);

    float4 v[4];
    float ss = 0.f;
    #pragma unroll
    for (int i = 0; i < 4; i++) {
        v[i] = wr[lane + i * 32];
        ss += v[i].x * v[i].x + v[i].y * v[i].y + v[i].z * v[i].z + v[i].w * v[i].w;
    }
    #pragma unroll
    for (int m = 16; m > 0; m >>= 1)
        ss += __shfl_xor_sync(0xffffffffu, ss, m);
    const float inv = 1.f / fmaxf(sqrtf(ss), 1e-12f);

    uint2* dst = reinterpret_cast<uint2*>(g_wh + (size_t)c * D_SZ);
    #pragma unroll
    for (int i = 0; i < 4; i++) {
        __half2 p0 = __floats2half2_rn(v[i].x * inv, v[i].y * inv);
        __half2 p1 = __floats2half2_rn(v[i].z * inv, v[i].w * inv);
        uint2 o;
        o.x = *reinterpret_cast<uint32_t*>(&p0);
        o.y = *reinterpret_cast<uint32_t*>(&p1);
        dst[lane + i * 32] = o;
    }
}

// ---------------------------------------------------------------------------
// Kernel 3: fused HMMA GEMM (fp16 in, fp16 acc) + streaming exp-sum epilogue.
// CTA 128x128xK512, 3-stage cp.async ring, BK=64, frag double-buffer,
// grid (m=4, n=782).
// ---------------------------------------------------------------------------
__global__ void __launch_bounds__(256, 1) gemm_fused_kernel() {
    extern __shared__ __align__(16) char smem[];
    const int tid = threadIdx.x;
    const int warp = tid >> 5;
    const int lane = tid & 31;
    const int wm = warp & 1;
    const int wn = warp >> 1;
    const int m0 = blockIdx.x * BM;
    const int n0 = blockIdx.y * BN;
    const uint32_t sb = smem_u32(smem);

    const __half* srcA = g_xh + (size_t)m0 * D_SZ;
    const __half* srcB = g_wh + (size_t)n0 * D_SZ;

    uint32_t acc[4][4][2];
    #pragma unroll
    for (int a = 0; a < 4; a++)
        #pragma unroll
        for (int b = 0; b < 4; b++) { acc[a][b][0] = 0u; acc[a][b][1] = 0u; }

    // stage loader: 2048 cp16 (A: 128x64 halves, B: 128x64 halves), 8/thread
    auto load_stage = [&](int stage, int k0) {
        const uint32_t dst = sb + (uint32_t)stage * STAGE_B;
        #pragma unroll
        for (int j = 0; j < 8; j++) {
            int idx = tid + 256 * j;            // 0..2047
            int row = (idx >> 3) & 127;
            int piece = idx & 7;
            uint32_t doff = (uint32_t)(row * (PITCH * 2) + piece * 16);
            if (idx < 1024)
                cp16(dst + doff, srcA + (size_t)row * D_SZ + k0 + piece * 8);
            else
                cp16(dst + B_PART + doff, srcB + (size_t)row * D_SZ + k0 + piece * 8);
        }
    };

    load_stage(0, 0);
    CP_COMMIT();
    load_stage(1, BK);
    CP_COMMIT();

    const int lrow = lane & 15;
    const int lcol = (lane >> 4) * 8;

    // double-buffered fragments
    uint32_t af[2][4][4], bf[2][2][4];
    auto ldfrags = [&](uint32_t aoff, uint32_t boff, int kk, int buf) {
        #pragma unroll
        for (int mt = 0; mt < 4; mt++)
            ldsm4(af[buf][mt], aoff + (uint32_t)((wm * 64 + mt * 16 + lrow) * PITCH + kk + lcol) * 2);
        #pragma unroll
        for (int nt2 = 0; nt2 < 2; nt2++)
            ldsm4(bf[buf][nt2], boff + (uint32_t)((wn * 32 + nt2 * 16 + lrow) * PITCH + kk + lcol) * 2);
    };

    for (int k = 0; k < NK; k++) {
        if (k == NK - 1) { CP_WAIT(0); } else { CP_WAIT(1); }
        __syncthreads();

        const uint32_t aoff = sb + (uint32_t)(k % NSTAGE) * STAGE_B;
        const uint32_t boff = aoff + B_PART;

        ldfrags(aoff, boff, 0, 0);
        #pragma unroll
        for (int c4 = 0; c4 < 4; c4++) {           // kk = c4*16
            const int cur = c4 & 1;
            if (c4 < 3) ldfrags(aoff, boff, (c4 + 1) * 16, cur ^ 1);
            #pragma unroll
            for (int mt = 0; mt < 4; mt++) {
                #pragma unroll
                for (int nt = 0; nt < 4; nt++) {
                    const uint32_t* bb = bf[cur][nt >> 1];
                    uint32_t b0 = (nt & 1) ? bb[1] : bb[0];
                    uint32_t b1 = (nt & 1) ? bb[3] : bb[2];
                    mma16816h(acc[mt][nt], af[cur][mt], b0, b1);
                }
            }
        }
        __syncthreads();   // all warps done reading stage k before it is refilled

        if (k + 2 < NK) {
            load_stage((k + 2) % NSTAGE, (k + 2) * BK);
            CP_COMMIT();
        }
    }

    // ---- epilogue: exp-sum per batch row, atomic into g_rowsum -------------
    // acc regs: reg0 = (row r, cols c0,c0+1), reg1 = (row r+8, cols c0,c0+1)
    const bool edge = (n0 + BN > C_SZ);
    const int rbase = m0 + wm * 64 + (lane >> 2);
    const int cbase = n0 + wn * 32 + 2 * (lane & 3);

    #pragma unroll
    for (int mt = 0; mt < 4; mt++) {
        float es0 = 0.f, es1 = 0.f;
        #pragma unroll
        for (int nt = 0; nt < 4; nt++) {
            const int c0 = cbase + nt * 8;
            float2 f01 = __half22float2(*reinterpret_cast<__half2*>(&acc[mt][nt][0]));
            float2 f23 = __half22float2(*reinterpret_cast<__half2*>(&acc[mt][nt][1]));
            if (!edge) {
                es0 += __expf(fmaf(f01.x, S_SCALE, -LMAX));
                es0 += __expf(fmaf(f01.y, S_SCALE, -LMAX));
                es1 += __expf(fmaf(f23.x, S_SCALE, -LMAX));
                es1 += __expf(fmaf(f23.y, S_SCALE, -LMAX));
            } else {
                if (c0 < C_SZ)     { es0 += __expf(fmaf(f01.x, S_SCALE, -LMAX));
                                     es1 += __expf(fmaf(f23.x, S_SCALE, -LMAX)); }
                if (c0 + 1 < C_SZ) { es0 += __expf(fmaf(f01.y, S_SCALE, -LMAX));
                                     es1 += __expf(fmaf(f23.y, S_SCALE, -LMAX)); }
            }
        }
        es0 += __shfl_xor_sync(0xffffffffu, es0, 1);
        es0 += __shfl_xor_sync(0xffffffffu, es0, 2);
        es1 += __shfl_xor_sync(0xffffffffu, es1, 1);
        es1 += __shfl_xor_sync(0xffffffffu, es1, 2);
        if ((lane & 3) == 0) {
            atomicAdd(&g_rowsum[rbase + mt * 16], es0);
            atomicAdd(&g_rowsum[rbase + mt * 16 + 8], es1);
        }
    }
}

// ---------------------------------------------------------------------------
// Kernel 4: finalize — exact fp32 target dot + target norm, margin swap, nll;
// atomic mean accumulation into out[0] (zeroed by xnorm).
// ---------------------------------------------------------------------------
__global__ void finalize_kernel(const float* __restrict__ w,
                                const int* __restrict__ tgt,
                                float* __restrict__ out) {
    const int b = blockIdx.x;
    const int tid = threadIdx.x;   // 256
    __shared__ float sd[256], sn[256];

    const int t = tgt[b];
    const float* wr = w + (size_t)t * D_SZ;
    const float* xr = g_xn + (size_t)b * D_SZ;
    float w0 = wr[tid], w1 = wr[tid + 256];
    sd[tid] = xr[tid] * w0 + xr[tid + 256] * w1;
    sn[tid] = w0 * w0 + w1 * w1;
    __syncthreads();
    #pragma unroll
    for (int off = 128; off > 0; off >>= 1) {
        if (tid < off) { sd[tid] += sd[tid + off]; sn[tid] += sn[tid + off]; }
        __syncthreads();
    }

    if (tid == 0) {
        float winv = 1.f / fmaxf(sqrtf(sn[0]), 1e-12f);
        float cosv = sd[0] * winv;
        float sinv = sqrtf(fmaxf(1.f - cosv * cosv, 0.f));
        float phi = cosv * COS_M - sinv * SIN_M;
        float adj = (cosv > 0.f) ? phi : cosv;          // easy margin
        float lt = S_SCALE * adj;
        float lo = S_SCALE * cosv;
        float s2 = g_rowsum[b] - expf(lo - LMAX) + expf(lt - LMAX);
        float nll = LMAX + logf(s2) - lt;
        atomicAdd(out, nll * (1.f / (float)B_SZ));
    }
}

// ---------------------------------------------------------------------------
extern "C" void kernel_launch(void* const* d_in, const int* in_sizes, int n_in,
                              void* d_out, int out_size) {
    const float* x = (const float*)d_in[0];
    const float* w = (const float*)d_in[1];
    const int* tgt = (const int*)d_in[2];
    float* out = (float*)d_out;

    cudaFuncSetAttribute(gemm_fused_kernel,
                         cudaFuncAttributeMaxDynamicSharedMemorySize, SMEM_BYTES);

    xnorm_kernel<<<B_SZ, 128>>>(x, out);
    wconv_kernel<<<C_SZ / 8, 256>>>(w);
    dim3 grid(B_SZ / BM, NTILES_N);
    gemm_fused_kernel<<<grid, 256, SMEM_BYTES>>>();
    finalize_kernel<<<B_SZ, 256>>>(w, tgt, out);
}